// round 12
// baseline (speedup 1.0000x reference)
#include <cuda_runtime.h>
#include <math.h>

// Problem constants (fixed shapes from reference setup_inputs)
#define B_      4
#define C_      256
#define P_      65536          // H*W = 256*256
#define NSEG    32             // object ids 1..32
#define PT      1024           // pixels per tile
#define TILES_PER_B (P_ / PT)  // 64
#define NBLK1   (B_ * TILES_PER_B)  // 256 pooling blocks (+1 wf block)
#define THREADS1 256
#define NQ      (C_ / 4)       // 64 channel-quads

// Global segmented maxima as non-negative float bit-patterns: [b][seg][c], 128 KB.
// INVARIANT: zero at kernel_launch entry (zero at module load; epilogue re-zeros).
__device__ int g_gmax[B_ * NSEG * C_];
// Fused MLP weight Wf = w1@w2 [256][4] and bias = b2 + b1@w2 [4]
__device__ float g_wf[C_ * 4];
__device__ float g_bias[4];
// Arrival counter for the in-kernel last-block-done barrier (reset by epilogue).
__device__ int g_counter;

// ---------------------------------------------------------------------------
// Single fused kernel, 3 CTAs/SM (reg-capped):
//  - Blocks 0..NBLK1-1: per-tile segmented max (accum [cquad][id][4ch], LDS.128
//    snapshot + shared atomicMax on non-negative float bits; stale-safe since
//    monotone), 4+4 double-buffered loads, REDG.MAX flush to g_gmax.
//  - Block NBLK1: computes Wf = w1@w2 and bias = b2 + b1@w2 (hidden in wave).
//  - ALL blocks fence + increment g_counter; the 257th arrival runs the MLP
//    epilogue (Wf staged via shared to keep reg count low), then re-zeros
//    g_gmax and resets g_counter.
// ---------------------------------------------------------------------------
__global__ __launch_bounds__(THREADS1, 3)
void fused_kernel(const float* __restrict__ enc, const int* __restrict__ masks,
                  const float* __restrict__ w1, const float* __restrict__ b1,
                  const float* __restrict__ w2, const float* __restrict__ b2,
                  float* __restrict__ out) {
    __shared__ int4 accum4[NQ * 33];            // 33 KB (pooling blocks only)
    __shared__ int s_ticket;
    int* accum = reinterpret_cast<int*>(accum4);

    const int blk  = blockIdx.x;
    const int tid  = threadIdx.x;
    const int warp = tid >> 5;
    const int lane = tid & 31;

    if (blk == NBLK1) {
        // ---- fused-weight block: 8 warps cover 256 c-rows, 32 rows each ----
        for (int r = 0; r < 32; r++) {
            const int c = r * 8 + warp;
            float a0 = 0.f, a1 = 0.f, a2 = 0.f, a3 = 0.f;
            #pragma unroll
            for (int k = 0; k < 4; k++) {
                const int j = lane + 32 * k;
                const float a = w1[c * 128 + j];
                const float4 wr = *reinterpret_cast<const float4*>(w2 + j * 4);
                a0 = fmaf(a, wr.x, a0); a1 = fmaf(a, wr.y, a1);
                a2 = fmaf(a, wr.z, a2); a3 = fmaf(a, wr.w, a3);
            }
            #pragma unroll
            for (int d = 16; d >= 1; d >>= 1) {
                a0 += __shfl_xor_sync(0xffffffffu, a0, d);
                a1 += __shfl_xor_sync(0xffffffffu, a1, d);
                a2 += __shfl_xor_sync(0xffffffffu, a2, d);
                a3 += __shfl_xor_sync(0xffffffffu, a3, d);
            }
            if (lane == 0)
                *reinterpret_cast<float4*>(g_wf + c * 4) = make_float4(a0, a1, a2, a3);
        }
        if (warp == 0) {
            float s0 = 0.f, s1 = 0.f, s2 = 0.f, s3 = 0.f;
            #pragma unroll
            for (int k = 0; k < 4; k++) {
                const int j = lane + 32 * k;
                const float bv = b1[j];
                const float4 wr = *reinterpret_cast<const float4*>(w2 + j * 4);
                s0 = fmaf(bv, wr.x, s0); s1 = fmaf(bv, wr.y, s1);
                s2 = fmaf(bv, wr.z, s2); s3 = fmaf(bv, wr.w, s3);
            }
            #pragma unroll
            for (int d = 16; d >= 1; d >>= 1) {
                s0 += __shfl_xor_sync(0xffffffffu, s0, d);
                s1 += __shfl_xor_sync(0xffffffffu, s1, d);
                s2 += __shfl_xor_sync(0xffffffffu, s2, d);
                s3 += __shfl_xor_sync(0xffffffffu, s3, d);
            }
            if (lane == 0) {
                g_bias[0] = s0 + b2[0];
                g_bias[1] = s1 + b2[1];
                g_bias[2] = s2 + b2[2];
                g_bias[3] = s3 + b2[3];
            }
        }
    } else {
        // ---- pooling block ----
        const int b    = blk / TILES_PER_B;
        const int tile = blk % TILES_PER_B;

        #pragma unroll
        for (int i = tid; i < NQ * 33 * 4; i += THREADS1) accum[i] = 0;

        const int pbase = tile * PT;
        const int4 idv = reinterpret_cast<const int4*>(masks + (size_t)b * P_ + pbase)[tid];
        const int id0 = idv.x, id1 = idv.y, id2 = idv.z, id3 = idv.w;

        __syncthreads();

        const float* encb = enc + (size_t)b * C_ * P_ + pbase;

        #define LOADV(DST, CBASE)                                                   \
            _Pragma("unroll")                                                       \
            for (int u = 0; u < 4; u++)                                             \
                DST[u] = reinterpret_cast<const float4*>(encb + (size_t)((CBASE) + u) * P_)[tid];

        // one channel-quad (4 consecutive channels), 4 pixels per thread
        #define CHECK_PIXEL(CQ, IDX, SRC, COMP)                                     \
        {                                                                           \
            const int4 cur = accum4[(CQ) * 33 + IDX];                               \
            const int base = ((CQ) * 33 + IDX) * 4; int a;                          \
            a = __float_as_int(SRC[0].COMP); if (a > cur.x) atomicMax(&accum[base+0], a); \
            a = __float_as_int(SRC[1].COMP); if (a > cur.y) atomicMax(&accum[base+1], a); \
            a = __float_as_int(SRC[2].COMP); if (a > cur.z) atomicMax(&accum[base+2], a); \
            a = __float_as_int(SRC[3].COMP); if (a > cur.w) atomicMax(&accum[base+3], a); \
        }

        #define PROCESS(SRC, CBASE)                                                 \
        {                                                                           \
            const int cq = (CBASE) >> 2;                                            \
            CHECK_PIXEL(cq, id0, SRC, x)                                            \
            CHECK_PIXEL(cq, id1, SRC, y)                                            \
            CHECK_PIXEL(cq, id2, SRC, z)                                            \
            CHECK_PIXEL(cq, id3, SRC, w)                                            \
        }

        float4 va[4], vb[4];
        LOADV(va, 0)
        #pragma unroll 1
        for (int c0 = 0; c0 < C_; c0 += 8) {
            LOADV(vb, c0 + 4)
            PROCESS(va, c0)
            if (c0 + 8 < C_) { LOADV(va, c0 + 8) }
            PROCESS(vb, c0 + 4)
        }
        #undef LOADV
        #undef PROCESS
        #undef CHECK_PIXEL

        __syncthreads();

        // flush straight to global maxima (drop id 0 = background); REDG.MAX.
        #pragma unroll
        for (int i = tid; i < NSEG * C_; i += THREADS1) {
            const int s = i >> 8;        // 0..31
            const int c = i & 255;       // 0..255
            atomicMax(&g_gmax[(b * NSEG + s) * C_ + c],
                      accum[((c >> 2) * 33 + s + 1) * 4 + (c & 3)]);
        }
    }

    // ---- arrival: last block (ticket == NBLK1, i.e. 257th) runs the epilogue ----
    __threadfence();
    __syncthreads();
    if (tid == 0) s_ticket = atomicAdd(&g_counter, 1);
    __syncthreads();
    if (s_ticket != NBLK1) return;

    __threadfence();   // acquire: all other blocks' REDG + wf stores visible

    // stage Wf (4 KB) into shared, reusing the accumulator space
    float4* s_wf = reinterpret_cast<float4*>(accum4);   // s_wf[c] = Wf row c
    #pragma unroll
    for (int i = tid; i < C_; i += THREADS1)
        s_wf[i] = make_float4(__ldcg(&g_wf[i * 4 + 0]), __ldcg(&g_wf[i * 4 + 1]),
                              __ldcg(&g_wf[i * 4 + 2]), __ldcg(&g_wf[i * 4 + 3]));
    __syncthreads();
    const float bias0 = __ldcg(&g_bias[0]), bias1 = __ldcg(&g_bias[1]),
                bias2 = __ldcg(&g_bias[2]), bias3 = __ldcg(&g_bias[3]);

    // warp w handles (b,seg) rows w*16 .. w*16+15
    for (int i = 0; i < 16; i++) {
        const int bn = warp * 16 + i;
        const int4* row = reinterpret_cast<const int4*>(g_gmax + bn * C_);
        const int4 ga = __ldcg(row + lane);        // c = lane*4 + j
        const int4 gb = __ldcg(row + 32 + lane);   // c = 128 + lane*4 + j

        float a0 = 0.f, a1 = 0.f, a2 = 0.f, a3 = 0.f;
        #define ACCUM(VAL, CC)                                                   \
        {                                                                        \
            const float v = __int_as_float(VAL);                                 \
            const float4 w = s_wf[CC];                                           \
            a0 = fmaf(v, w.x, a0); a1 = fmaf(v, w.y, a1);                        \
            a2 = fmaf(v, w.z, a2); a3 = fmaf(v, w.w, a3);                        \
        }
        ACCUM(ga.x, lane * 4 + 0) ACCUM(ga.y, lane * 4 + 1)
        ACCUM(ga.z, lane * 4 + 2) ACCUM(ga.w, lane * 4 + 3)
        ACCUM(gb.x, 128 + lane * 4 + 0) ACCUM(gb.y, 128 + lane * 4 + 1)
        ACCUM(gb.z, 128 + lane * 4 + 2) ACCUM(gb.w, 128 + lane * 4 + 3)
        #undef ACCUM

        #pragma unroll
        for (int d = 16; d >= 1; d >>= 1) {
            a0 += __shfl_xor_sync(0xffffffffu, a0, d);
            a1 += __shfl_xor_sync(0xffffffffu, a1, d);
            a2 += __shfl_xor_sync(0xffffffffu, a2, d);
            a3 += __shfl_xor_sync(0xffffffffu, a3, d);
        }
        if (lane == 0) {
            out[bn * 4 + 0] = 1.0f / (1.0f + expf(-(a0 + bias0)));
            out[bn * 4 + 1] = 1.0f / (1.0f + expf(-(a1 + bias1)));
            out[bn * 4 + 2] = 1.0f / (1.0f + expf(-(a2 + bias2)));
            out[bn * 4 + 3] = 1.0f / (1.0f + expf(-(a3 + bias3)));
        }
    }

    // restore zero invariant: each warp zeroes the rows it consumed
    const int4 z4 = make_int4(0, 0, 0, 0);
    for (int i = 0; i < 16; i++) {
        int4* row = reinterpret_cast<int4*>(g_gmax + (warp * 16 + i) * C_);
        row[lane]      = z4;
        row[32 + lane] = z4;
    }
    if (tid == 0) g_counter = 0;   // all 257 arrivals already counted
}

// ---------------------------------------------------------------------------
extern "C" void kernel_launch(void* const* d_in, const int* in_sizes, int n_in,
                              void* d_out, int out_size) {
    const float* enc   = (const float*)d_in[0];  // [4,256,256,256] f32
    const float* w1    = (const float*)d_in[1];  // [256,128]
    const float* b1    = (const float*)d_in[2];  // [128]
    const float* w2    = (const float*)d_in[3];  // [128,4]
    const float* b2    = (const float*)d_in[4];  // [4]
    const int*   masks = (const int*)d_in[5];    // [4,1,256,256] i32

    fused_kernel<<<NBLK1 + 1, THREADS1>>>(enc, masks, w1, b1, w2, b2, (float*)d_out);
}

// round 13
// speedup vs baseline: 1.3773x; 1.3773x over previous
#include <cuda_runtime.h>
#include <math.h>

// Problem constants (fixed shapes from reference setup_inputs)
#define B_      4
#define C_      256
#define P_      65536          // H*W = 256*256
#define NSEG    32             // object ids 1..32
#define PT      1024           // pixels per tile
#define TILES_PER_B (P_ / PT)  // 64
#define CH      128            // channels per block (tile split in 2)
#define NQH     (CH / 4)       // 32 channel-quads per block
#define NBLK1   (B_ * TILES_PER_B * 2)  // 512 pooling blocks (+1 wf block)
#define THREADS1 256

// Per-tile partial maxima [b][seg][tile][c]: 4*32*64*256 floats = 8 MB.
// Each pooling block writes only its 128-channel half of its tile's rows.
__device__ float g_scratch[(size_t)B_ * NSEG * TILES_PER_B * C_];
// Fused MLP weight Wf = w1@w2 [256][4] and bias = b2 + b1@w2 [4]
__device__ float g_wf[C_ * 4];
__device__ float g_bias[4];

// ---------------------------------------------------------------------------
// Phase 1: per-(tile, channel-half) segmented max. accum [cquad][id][4ch];
// one LDS.128 snapshots 4 channels' maxima for a pixel's id. Non-negative
// float bits (init 0 == clamp at 0; int cmp == float cmp); stale snapshots
// safe (monotone). 4+4 double-buffered loads, 56 regs -> 4-CTA cap; grid 512
// gives ~3.5 CTAs/SM (~28 warps) for full memory-level parallelism.
// The LAST block computes Wf = w1@w2 and bias = b2 + b1@w2 instead.
// ---------------------------------------------------------------------------
__global__ __launch_bounds__(THREADS1, 4)
void seg_pool_kernel(const float* __restrict__ enc, const int* __restrict__ masks,
                     const float* __restrict__ w1, const float* __restrict__ b1,
                     const float* __restrict__ w2, const float* __restrict__ b2) {
    const int blk  = blockIdx.x;
    const int tid  = threadIdx.x;
    const int warp = tid >> 5;
    const int lane = tid & 31;

    if (blk == NBLK1) {
        // ---- fused-weight block: 8 warps cover 256 c-rows, 32 rows each ----
        for (int r = 0; r < 32; r++) {
            const int c = r * 8 + warp;
            float a0 = 0.f, a1 = 0.f, a2 = 0.f, a3 = 0.f;
            #pragma unroll
            for (int k = 0; k < 4; k++) {
                const int j = lane + 32 * k;
                const float a = w1[c * 128 + j];
                const float4 wr = *reinterpret_cast<const float4*>(w2 + j * 4);
                a0 = fmaf(a, wr.x, a0); a1 = fmaf(a, wr.y, a1);
                a2 = fmaf(a, wr.z, a2); a3 = fmaf(a, wr.w, a3);
            }
            #pragma unroll
            for (int d = 16; d >= 1; d >>= 1) {
                a0 += __shfl_xor_sync(0xffffffffu, a0, d);
                a1 += __shfl_xor_sync(0xffffffffu, a1, d);
                a2 += __shfl_xor_sync(0xffffffffu, a2, d);
                a3 += __shfl_xor_sync(0xffffffffu, a3, d);
            }
            if (lane == 0)
                *reinterpret_cast<float4*>(g_wf + c * 4) = make_float4(a0, a1, a2, a3);
        }
        if (warp == 0) {
            float s0 = 0.f, s1 = 0.f, s2 = 0.f, s3 = 0.f;
            #pragma unroll
            for (int k = 0; k < 4; k++) {
                const int j = lane + 32 * k;
                const float bv = b1[j];
                const float4 wr = *reinterpret_cast<const float4*>(w2 + j * 4);
                s0 = fmaf(bv, wr.x, s0); s1 = fmaf(bv, wr.y, s1);
                s2 = fmaf(bv, wr.z, s2); s3 = fmaf(bv, wr.w, s3);
            }
            #pragma unroll
            for (int d = 16; d >= 1; d >>= 1) {
                s0 += __shfl_xor_sync(0xffffffffu, s0, d);
                s1 += __shfl_xor_sync(0xffffffffu, s1, d);
                s2 += __shfl_xor_sync(0xffffffffu, s2, d);
                s3 += __shfl_xor_sync(0xffffffffu, s3, d);
            }
            if (lane == 0) {
                g_bias[0] = s0 + b2[0];
                g_bias[1] = s1 + b2[1];
                g_bias[2] = s2 + b2[2];
                g_bias[3] = s3 + b2[3];
            }
        }
        return;
    }

    __shared__ int4 accum4[NQH * 33];           // 32*33*16 B = 16.9 KB
    int* accum = reinterpret_cast<int*>(accum4);

    // block -> (batch, tile, channel-half)
    const int b    = blk / (TILES_PER_B * 2);
    const int rem  = blk % (TILES_PER_B * 2);
    const int tile = rem >> 1;
    const int half = rem & 1;                   // 0: channels 0..127, 1: 128..255
    const int choff = half * CH;

    #pragma unroll
    for (int i = tid; i < NQH * 33 * 4; i += THREADS1) accum[i] = 0;

    const int pbase = tile * PT;
    const int4 idv = reinterpret_cast<const int4*>(masks + (size_t)b * P_ + pbase)[tid];
    const int id0 = idv.x, id1 = idv.y, id2 = idv.z, id3 = idv.w;

    __syncthreads();

    const float* encb = enc + ((size_t)b * C_ + choff) * P_ + pbase;

    #define LOADV(DST, CBASE)                                                   \
        _Pragma("unroll")                                                       \
        for (int u = 0; u < 4; u++)                                             \
            DST[u] = reinterpret_cast<const float4*>(encb + (size_t)((CBASE) + u) * P_)[tid];

    // one channel-quad (4 consecutive channels), 4 pixels per thread
    #define CHECK_PIXEL(CQ, IDX, SRC, COMP)                                     \
    {                                                                           \
        const int4 cur = accum4[(CQ) * 33 + IDX];                               \
        const int base = ((CQ) * 33 + IDX) * 4; int a;                          \
        a = __float_as_int(SRC[0].COMP); if (a > cur.x) atomicMax(&accum[base+0], a); \
        a = __float_as_int(SRC[1].COMP); if (a > cur.y) atomicMax(&accum[base+1], a); \
        a = __float_as_int(SRC[2].COMP); if (a > cur.z) atomicMax(&accum[base+2], a); \
        a = __float_as_int(SRC[3].COMP); if (a > cur.w) atomicMax(&accum[base+3], a); \
    }

    #define PROCESS(SRC, CBASE)                                                 \
    {                                                                           \
        const int cq = (CBASE) >> 2;                                            \
        CHECK_PIXEL(cq, id0, SRC, x)                                            \
        CHECK_PIXEL(cq, id1, SRC, y)                                            \
        CHECK_PIXEL(cq, id2, SRC, z)                                            \
        CHECK_PIXEL(cq, id3, SRC, w)                                            \
    }

    float4 va[4], vb[4];
    LOADV(va, 0)
    #pragma unroll 1
    for (int c0 = 0; c0 < CH; c0 += 8) {
        LOADV(vb, c0 + 4)
        PROCESS(va, c0)
        if (c0 + 8 < CH) { LOADV(va, c0 + 8) }
        PROCESS(vb, c0 + 4)
    }
    #undef LOADV
    #undef PROCESS
    #undef CHECK_PIXEL

    __syncthreads();

    // flush this half's channels to [b][seg][tile][c] (drop id 0 = background)
    #pragma unroll
    for (int i = tid; i < NSEG * CH; i += THREADS1) {
        const int s  = i >> 7;       // 0..31
        const int cl = i & 127;      // local channel 0..127
        g_scratch[(((size_t)b * NSEG + s) * TILES_PER_B + tile) * C_ + choff + cl] =
            __int_as_float(accum[((cl >> 2) * 33 + s + 1) * 4 + (cl & 3)]);
    }
}

// ---------------------------------------------------------------------------
// Phase 2: max over 64 tile-partials per (b,seg), then one multiply by the
// precomputed fused weight + 4-warp tree sum + sigmoid.
// ---------------------------------------------------------------------------
__global__ __launch_bounds__(1024)
void reduce_mlp_kernel(float* __restrict__ out) {
    __shared__ float part[16][C_];   // 16 KB
    __shared__ float mlp[4][C_];     // 4 KB

    const int blk = blockIdx.x;      // b*NSEG + n
    const int b   = blk / NSEG;
    const int n   = blk % NSEG;
    const int tid = threadIdx.x;
    const int c4    = (tid & 63) * 4;
    const int chunk = tid >> 6;         // 0..15, each owns 4 tiles
    const int c     = tid >> 2;         // 0..255
    const int o     = tid & 3;          // 0..3

    const float wf = g_wf[tid];         // Wf[c][o], coalesced

    const float* base = g_scratch
        + (((size_t)b * NSEG + n) * TILES_PER_B + (size_t)chunk * 4) * C_ + c4;
    float4 v[4];
    #pragma unroll
    for (int t = 0; t < 4; t++)
        v[t] = *reinterpret_cast<const float4*>(base + (size_t)t * C_);
    float4 m = v[0];
    #pragma unroll
    for (int t = 1; t < 4; t++) {
        m.x = fmaxf(m.x, v[t].x); m.y = fmaxf(m.y, v[t].y);
        m.z = fmaxf(m.z, v[t].z); m.w = fmaxf(m.w, v[t].w);
    }
    *reinterpret_cast<float4*>(&part[chunk][c4]) = m;
    __syncthreads();

    #pragma unroll
    for (int stride = 8; stride >= 1; stride >>= 1) {
        if (chunk < stride) {
            float4 a = *reinterpret_cast<const float4*>(&part[chunk][c4]);
            float4 bb = *reinterpret_cast<const float4*>(&part[chunk + stride][c4]);
            a.x = fmaxf(a.x, bb.x); a.y = fmaxf(a.y, bb.y);
            a.z = fmaxf(a.z, bb.z); a.w = fmaxf(a.w, bb.w);
            *reinterpret_cast<float4*>(&part[chunk][c4]) = a;
        }
        __syncthreads();
    }
    // part[0][0..255] == pooled

    mlp[o][c] = part[0][c] * wf;
    __syncthreads();

    const int wid = tid >> 5, lane = tid & 31;
    if (wid < 4) {
        float s = 0.0f;
        #pragma unroll
        for (int k = 0; k < 8; k++) s += mlp[wid][lane + 32 * k];
        #pragma unroll
        for (int d = 16; d >= 1; d >>= 1) s += __shfl_xor_sync(0xffffffffu, s, d);
        if (lane == 0)
            out[blk * 4 + wid] = 1.0f / (1.0f + expf(-(s + g_bias[wid])));
    }
}

// ---------------------------------------------------------------------------
extern "C" void kernel_launch(void* const* d_in, const int* in_sizes, int n_in,
                              void* d_out, int out_size) {
    const float* enc   = (const float*)d_in[0];  // [4,256,256,256] f32
    const float* w1    = (const float*)d_in[1];  // [256,128]
    const float* b1    = (const float*)d_in[2];  // [128]
    const float* w2    = (const float*)d_in[3];  // [128,4]
    const float* b2    = (const float*)d_in[4];  // [4]
    const int*   masks = (const int*)d_in[5];    // [4,1,256,256] i32

    seg_pool_kernel<<<NBLK1 + 1, THREADS1>>>(enc, masks, w1, b1, w2, b2);
    reduce_mlp_kernel<<<B_ * NSEG, 1024>>>((float*)d_out);
}